// round 10
// baseline (speedup 1.0000x reference)
#include <cuda_runtime.h>
#include <cuda_bf16.h>
#include <stdint.h>

#define M_SIZE 4096
#define NMODES 128
#define BATCH  32
#define CH     256
#define NROWS  (BATCH*CH)   // 8192
#define NC     (2*NMODES)   // 256
#define TH     2048         // folded K

// ---------------- device scratch (allocation-free globals) ----------------
__device__ __nv_bfloat16 g_u_h[(size_t)NROWS*TH], g_u_l[(size_t)NROWS*TH];   // x fold planes
__device__ __nv_bfloat16 g_v_h[(size_t)NROWS*TH], g_v_l[(size_t)NROWS*TH];
__device__ __nv_bfloat16 g_cosT_h[NMODES*TH], g_cosT_l[NMODES*TH];           // fwd B [m][t]
__device__ __nv_bfloat16 g_sinT_h[NMODES*TH], g_sinT_l[NMODES*TH];           // -sin
__device__ __nv_bfloat16 g_Bic_h[(size_t)TH*NMODES], g_Bic_l[(size_t)TH*NMODES]; // inv B [t][m]
__device__ __nv_bfloat16 g_Bis_h[(size_t)TH*NMODES], g_Bis_l[(size_t)TH*NMODES];
__device__ __nv_bfloat16 g_xT_h[(size_t)NC*NROWS],  g_xT_l[(size_t)NC*NROWS];    // xft [c][row]
__device__ __nv_bfloat16 gWre_h[(size_t)NMODES*CH*CH], gWre_l[(size_t)NMODES*CH*CH];
__device__ __nv_bfloat16 gWim_h[(size_t)NMODES*CH*CH], gWim_l[(size_t)NMODES*CH*CH];
__device__ __nv_bfloat16 g_ore_h[(size_t)NROWS*NMODES], g_ore_l[(size_t)NROWS*NMODES];
__device__ __nv_bfloat16 g_oim_h[(size_t)NROWS*NMODES], g_oim_l[(size_t)NROWS*NMODES];

// ---------------- helpers ----------------
__device__ __forceinline__ uint32_t smem_u32(const void* p) {
    uint32_t a;
    asm("{ .reg .u64 t; cvta.to.shared.u64 t, %1; cvt.u32.u64 %0, t; }" : "=r"(a) : "l"(p));
    return a;
}
#define SW(o) ((uint32_t)(o) ^ ((((uint32_t)(o)) >> 3) & 0x70))

#define CP16(d, s)  asm volatile("cp.async.cg.shared.global [%0], [%1], 16;" :: "r"(d), "l"(s))
#define CP_COMMIT() asm volatile("cp.async.commit_group;")
#define CP_WAIT0()  asm volatile("cp.async.wait_group 0;")

#define LDSM4(R, addr) \
    asm volatile("ldmatrix.sync.aligned.m8n8.x4.shared.b16 {%0,%1,%2,%3}, [%4];" \
        : "=r"((R)[0]), "=r"((R)[1]), "=r"((R)[2]), "=r"((R)[3]) : "r"(addr))

#define MMA4(C, A, b0, b1) \
    asm volatile("mma.sync.aligned.m16n8k16.row.col.f32.bf16.bf16.f32 " \
        "{%0,%1,%2,%3},{%4,%5,%6,%7},{%8,%9},{%0,%1,%2,%3};" \
        : "+f"((C)[0]), "+f"((C)[1]), "+f"((C)[2]), "+f"((C)[3]) \
        : "r"((A)[0]), "r"((A)[1]), "r"((A)[2]), "r"((A)[3]), "r"(b0), "r"(b1))

__device__ __forceinline__ void split_bf16(float v, __nv_bfloat16& h, __nv_bfloat16& l) {
    h = __float2bfloat16(v);
    l = __float2bfloat16(v - __bfloat162float(h));
}
__device__ __forceinline__ uint2 pack4(__nv_bfloat16 a, __nv_bfloat16 b,
                                       __nv_bfloat16 c, __nv_bfloat16 d) {
    __nv_bfloat162 p = __halves2bfloat162(a, b), q = __halves2bfloat162(c, d);
    return make_uint2(*(uint32_t*)&p, *(uint32_t*)&q);
}
__device__ __forceinline__ float lrelu(float v) { return v >= 0.f ? v : 0.2f * v; }

// ---------------------------------------------------------------------------
// Fold prepass: u = x[t]+x[M-t], v = x[t]-x[M-t], t=0..2047 (t=0 mirror := 0)
// One row per block, 256 threads, 2 groups of 4.
// ---------------------------------------------------------------------------
__global__ void __launch_bounds__(256) k_xsplit_fold(const float* __restrict__ x) {
    const int row = blockIdx.x;
    const float* xr = x + (size_t)row * M_SIZE;
#pragma unroll
    for (int it = 0; it < 2; it++) {
        int g = (threadIdx.x + it * 256) * 4;
        float4 f = *(const float4*)(xr + g);
        float m0 = (g == 0) ? 0.f : xr[M_SIZE - g];
        float m1 = xr[M_SIZE - g - 1];
        float m2 = xr[M_SIZE - g - 2];
        float m3 = xr[M_SIZE - g - 3];
        float u0 = f.x + m0, u1 = f.y + m1, u2 = f.z + m2, u3 = f.w + m3;
        float v0 = f.x - m0, v1 = f.y - m1, v2 = f.z - m2, v3 = f.w - m3;
        __nv_bfloat16 h0,l0,h1,l1,h2,l2,h3,l3;
        size_t dst = (size_t)row * TH + g;
        split_bf16(u0,h0,l0); split_bf16(u1,h1,l1); split_bf16(u2,h2,l2); split_bf16(u3,h3,l3);
        *(uint2*)&g_u_h[dst] = pack4(h0,h1,h2,h3);
        *(uint2*)&g_u_l[dst] = pack4(l0,l1,l2,l3);
        split_bf16(v0,h0,l0); split_bf16(v1,h1,l1); split_bf16(v2,h2,l2); split_bf16(v3,h3,l3);
        *(uint2*)&g_v_h[dst] = pack4(h0,h1,h2,h3);
        *(uint2*)&g_v_l[dst] = pack4(l0,l1,l2,l3);
    }
}

// ---------------------------------------------------------------------------
// Basis tables (folded)
// ---------------------------------------------------------------------------
__global__ void k_basis_fwd() {   // [m][t], t fastest
    int idx = blockIdx.x * blockDim.x + threadIdx.x;   // 128*2048
    int m = idx >> 11, t = idx & (TH - 1);
    int r = (t * m) & (M_SIZE - 1);
    float s, c;
    sincospif((float)r * (1.0f / 2048.0f), &s, &c);
    __nv_bfloat16 h, l;
    split_bf16(c, h, l);  g_cosT_h[idx] = h; g_cosT_l[idx] = l;
    split_bf16(-s, h, l); g_sinT_h[idx] = h; g_sinT_l[idx] = l;
}
__global__ void k_basis_inv() {   // [t][m], m fastest
    int idx = blockIdx.x * blockDim.x + threadIdx.x;   // 2048*128
    int t = idx >> 7, m = idx & 127;
    int r = (t * m) & (M_SIZE - 1);
    float s, c;
    sincospif((float)r * (1.0f / 2048.0f), &s, &c);
    __nv_bfloat16 h, l;
    split_bf16(c, h, l);  g_Bic_h[idx] = h; g_Bic_l[idx] = l;
    split_bf16(-s, h, l); g_Bis_h[idx] = h; g_Bis_l[idx] = l;
}

// ---------------------------------------------------------------------------
// Weight transpose: w2[o][i][m] float2 -> planes [m][o][i] bf16 hi/lo.
// ---------------------------------------------------------------------------
__global__ void __launch_bounds__(256) k_wtransp(const float2* __restrict__ w2) {
    __shared__ float2 s[64][33];
    const int o  = blockIdx.z;
    const int i0 = blockIdx.x * 64;
    const int m0 = blockIdx.y * 32;
    const int tid = threadIdx.x;
#pragma unroll
    for (int j = 0; j < 8; j++) {
        int f = tid + j * 256;
        int ii = f >> 5, ml = f & 31;
        s[ii][ml] = w2[((size_t)o * CH + i0 + ii) * NMODES + m0 + ml];
    }
    __syncthreads();
#pragma unroll
    for (int j = 0; j < 2; j++) {
        int f = tid + j * 256;
        int ml = f >> 4, ig = (f & 15) * 4;
        float2 v0 = s[ig][ml], v1 = s[ig+1][ml], v2 = s[ig+2][ml], v3 = s[ig+3][ml];
        size_t dst = ((size_t)(m0 + ml) * CH + o) * CH + i0 + ig;
        __nv_bfloat16 h0,l0,h1,l1,h2,l2,h3,l3;
        split_bf16(v0.x,h0,l0); split_bf16(v1.x,h1,l1);
        split_bf16(v2.x,h2,l2); split_bf16(v3.x,h3,l3);
        *(uint2*)&gWre_h[dst] = pack4(h0,h1,h2,h3);
        *(uint2*)&gWre_l[dst] = pack4(l0,l1,l2,l3);
        split_bf16(v0.y,h0,l0); split_bf16(v1.y,h1,l1);
        split_bf16(v2.y,h2,l2); split_bf16(v3.y,h3,l3);
        *(uint2*)&gWim_h[dst] = pack4(h0,h1,h2,h3);
        *(uint2*)&gWim_l[dst] = pack4(l0,l1,l2,l3);
    }
}

// smem plane offsets for fwd (per 48KB buffer: A 64rows, B 128rows)
#define P_AH 0
#define P_AL 8192
#define P_BH 16384
#define P_BL 32768
#define BUFB 49152
#define SMEM_GEMM (2*BUFB)   // 96KB -> 2 CTAs/SM

// ---------------------------------------------------------------------------
// Forward folded DFT. reim=0: Re[m] = sum_t u[t]cos + x[2048](-1)^m
//                     reim=1: Im[m] = sum_t v[t](-sin)
// 256 threads; block 64 rows x 128 modes; warp grid 2x4, tile 32x32; K=2048.
// ---------------------------------------------------------------------------
__global__ void __launch_bounds__(256, 2) k_fwd(const float* __restrict__ x) {
    extern __shared__ char sm[];
    uint32_t sb = smem_u32(sm);
    const int tid = threadIdx.x, lane = tid & 31, wid = tid >> 5;
    const int wr = wid & 1, wc = wid >> 1;
    const int row0 = blockIdx.x * 64;
    const int reim = blockIdx.y;

    const __nv_bfloat16* Ah_src = reim ? g_v_h : g_u_h;
    const __nv_bfloat16* Al_src = reim ? g_v_l : g_u_l;
    const __nv_bfloat16* Bh_src = reim ? g_sinT_h : g_cosT_h;
    const __nv_bfloat16* Bl_src = reim ? g_sinT_l : g_cosT_l;

    uint32_t offA[2], offB[2];
#pragma unroll
    for (int mf = 0; mf < 2; mf++)
        offA[mf] = (wr*32 + mf*16 + (lane & 15)) * 128 + (lane >> 4) * 16;
#pragma unroll
    for (int p = 0; p < 2; p++)
        offB[p] = (wc*32 + p*16 + ((lane >> 4) << 3) + (lane & 7)) * 128
                + ((lane >> 3) & 1) * 16;

    float acc[2][4][4];
#pragma unroll
    for (int i = 0; i < 2; i++)
#pragma unroll
        for (int j = 0; j < 4; j++)
#pragma unroll
            for (int q = 0; q < 4; q++) acc[i][j][q] = 0.0f;

#define FWD_LOAD(dstb, kk) do {                                                   \
    _Pragma("unroll")                                                             \
    for (int j = 0; j < 4; j++) {                                                 \
        int f = tid + j * 256;                                                    \
        int plane = f >> 9, r = (f >> 3) & 63, cb = f & 7;                        \
        const __nv_bfloat16* src = (plane ? Al_src : Ah_src)                      \
                                 + (size_t)(row0 + r) * TH + (kk) + cb * 8;       \
        CP16((dstb) + P_AH + plane * 8192 + SW(r * 128 + cb * 16), src);          \
    }                                                                             \
    _Pragma("unroll")                                                             \
    for (int j = 0; j < 4; j++) {                                                 \
        int f = tid + j * 256;                                                    \
        int plane = f >> 9, r = (f >> 3) & 127, cb = f & 7;                       \
        const __nv_bfloat16* src = (plane ? Bl_src : Bh_src)                      \
                                 + (size_t)r * TH + (kk) + cb * 8;                \
        CP16((dstb) + P_BH + plane * 16384 + SW(r * 128 + cb * 16), src);         \
    }                                                                             \
    CP_COMMIT();                                                                  \
} while (0)
    // note: B loop covers 2 planes x 128 rows x 8 cb = 2048 -> j<8 with 256 thr;
    // fixed below with j<8 variant.
#undef FWD_LOAD
#define FWD_LOAD(dstb, kk) do {                                                   \
    _Pragma("unroll")                                                             \
    for (int j = 0; j < 4; j++) {                                                 \
        int f = tid + j * 256;                                                    \
        int plane = f >> 9, r = (f >> 3) & 63, cb = f & 7;                        \
        const __nv_bfloat16* src = (plane ? Al_src : Ah_src)                      \
                                 + (size_t)(row0 + r) * TH + (kk) + cb * 8;       \
        CP16((dstb) + P_AH + plane * 8192 + SW(r * 128 + cb * 16), src);          \
    }                                                                             \
    _Pragma("unroll")                                                             \
    for (int j = 0; j < 8; j++) {                                                 \
        int f = tid + j * 256;                                                    \
        int plane = f >> 10, r = (f >> 3) & 127, cb = f & 7;                      \
        const __nv_bfloat16* src = (plane ? Bl_src : Bh_src)                      \
                                 + (size_t)r * TH + (kk) + cb * 8;                \
        CP16((dstb) + P_BH + plane * 16384 + SW(r * 128 + cb * 16), src);         \
    }                                                                             \
    CP_COMMIT();                                                                  \
} while (0)

    FWD_LOAD(sb, 0);
    CP_WAIT0();
    __syncthreads();

    const int NCHUNK = TH / 64;   // 32
    for (int cc = 0; cc < NCHUNK; cc++) {
        uint32_t bb  = sb + (cc & 1) * BUFB;
        uint32_t nbb = sb + ((cc + 1) & 1) * BUFB;
        if (cc + 1 < NCHUNK) FWD_LOAD(nbb, (cc + 1) * 64);
#pragma unroll
        for (int ks = 0; ks < 4; ks++) {
            uint32_t Af[2][4], Bh[2][4], Bo[2][4];
#pragma unroll
            for (int mf = 0; mf < 2; mf++) LDSM4(Af[mf], bb + P_AH + SW(offA[mf] + ks * 32));
#pragma unroll
            for (int p = 0; p < 2; p++)    LDSM4(Bh[p],  bb + P_BH + SW(offB[p] + ks * 32));
#pragma unroll
            for (int mf = 0; mf < 2; mf++)
#pragma unroll
                for (int nf = 0; nf < 4; nf++)
                    MMA4(acc[mf][nf], Af[mf], Bh[nf>>1][(nf&1)*2], Bh[nf>>1][(nf&1)*2+1]);
#pragma unroll
            for (int p = 0; p < 2; p++)    LDSM4(Bo[p],  bb + P_BL + SW(offB[p] + ks * 32));
#pragma unroll
            for (int mf = 0; mf < 2; mf++)
#pragma unroll
                for (int nf = 0; nf < 4; nf++)
                    MMA4(acc[mf][nf], Af[mf], Bo[nf>>1][(nf&1)*2], Bo[nf>>1][(nf&1)*2+1]);
#pragma unroll
            for (int mf = 0; mf < 2; mf++) LDSM4(Af[mf], bb + P_AL + SW(offA[mf] + ks * 32));
#pragma unroll
            for (int mf = 0; mf < 2; mf++)
#pragma unroll
                for (int nf = 0; nf < 4; nf++)
                    MMA4(acc[mf][nf], Af[mf], Bh[nf>>1][(nf&1)*2], Bh[nf>>1][(nf&1)*2+1]);
        }
        CP_WAIT0();
        __syncthreads();
    }
#undef FWD_LOAD
    // ---- epilogue: (reim==0) add x[2048](-1)^m ; split; write xT[c][row] ----
#pragma unroll
    for (int mf = 0; mf < 2; mf++) {
        int row = row0 + wr*32 + mf*16 + (lane >> 2);
        float c20 = 0.f, c21 = 0.f;
        if (reim == 0) {
            c20 = x[(size_t)row * M_SIZE + 2048];
            c21 = x[(size_t)(row + 8) * M_SIZE + 2048];
        }
#pragma unroll
        for (int nf = 0; nf < 4; nf++) {
            int m = wc*32 + nf*8 + (lane & 3) * 2;   // even
#pragma unroll
            for (int q = 0; q < 4; q++) {
                int mm = m + (q & 1);
                int rr = row + (q >> 1) * 8;
                float corr = (q >> 1) ? c21 : c20;
                float v = acc[mf][nf][q] + ((q & 1) ? -corr : corr);
                __nv_bfloat16 h, l;
                split_bf16(v, h, l);
                size_t di = (size_t)(2 * mm + reim) * NROWS + rr;
                g_xT_h[di] = h; g_xT_l[di] = l;
            }
        }
    }
}

// ---------------------------------------------------------------------------
// MMA mode mixing (R9-proven loop). Epilogue -> separated re/im planes [row][m].
// ---------------------------------------------------------------------------
#define MX_REH 0
#define MX_REL 16384
#define MX_IMH 32768
#define MX_IML 49152
#define MW_BASE 65536
#define SMEM_MIX (MW_BASE + 32768)   // 96KB

__global__ void __launch_bounds__(256, 2) k_mixmma() {
    extern __shared__ char sm[];
    uint32_t sb = smem_u32(sm);
    const int tid = threadIdx.x, lane = tid & 31, wid = tid >> 5;
    const int wg = wid >> 2, wn = wid & 3;
    const int m  = blockIdx.x;
    const int o0 = blockIdx.y * 64;

#define MIX_LOADW(kk) do {                                                        \
    _Pragma("unroll")                                                             \
    for (int j = 0; j < 8; j++) {                                                 \
        int f = tid + j * 256;                                                    \
        int p = f >> 9, r = (f >> 3) & 63, cb = f & 7;                            \
        const __nv_bfloat16* src = (p == 0) ? gWre_h : (p == 1) ? gWre_l          \
                                 : (p == 2) ? gWim_h : gWim_l;                    \
        CP16(sb + MW_BASE + p * 8192 + SW(r * 128 + cb * 16),                     \
             src + ((size_t)m * CH + o0 + r) * CH + (kk) + cb * 8);               \
    }                                                                             \
    CP_COMMIT();                                                                  \
} while (0)

    {
        const __nv_bfloat16* srcs[4] = {
            g_xT_h + (size_t)(2 * m)     * NROWS,
            g_xT_l + (size_t)(2 * m)     * NROWS,
            g_xT_h + (size_t)(2 * m + 1) * NROWS,
            g_xT_l + (size_t)(2 * m + 1) * NROWS };
#pragma unroll
        for (int j = 0; j < 16; j++) {
            int f = tid + j * 256;
            int p = f >> 10, rem = f & 1023;
            int b = rem >> 5, cb32 = rem & 31;
            int chunk = cb32 >> 3, cb = cb32 & 7;
            CP16(sb + p * 16384 + chunk * 4096 + SW(b * 128 + cb * 16),
                 srcs[p] + (size_t)b * CH + cb32 * 8);
        }
        MIX_LOADW(0);
        CP_WAIT0();
    }
    __syncthreads();

    uint32_t offA[2], offB;
#pragma unroll
    for (int mf = 0; mf < 2; mf++)
        offA[mf] = (mf*16 + (lane & 15)) * 128 + (lane >> 4) * 16;
    offB = (wn*16 + ((lane >> 4) << 3) + (lane & 7)) * 128 + ((lane >> 3) & 1) * 16;

    const uint32_t b1 = wg ? 16384u : 0u;
    const uint32_t b2 = wg ? 0u : 16384u;

    float acc1[2][2][4], acc2[2][2][4];
#pragma unroll
    for (int i = 0; i < 2; i++)
#pragma unroll
        for (int j = 0; j < 2; j++)
#pragma unroll
            for (int q = 0; q < 4; q++) { acc1[i][j][q] = 0.0f; acc2[i][j][q] = 0.0f; }

    for (int cc = 0; cc < 4; cc++) {
        uint32_t wb = sb + MW_BASE;
#pragma unroll
        for (int ks = 0; ks < 4; ks++) {
#pragma unroll
            for (int combo = 0; combo < 2; combo++) {
                uint32_t ah = sb + (combo ? MX_IMH : MX_REH) + cc * 4096;
                uint32_t al = sb + (combo ? MX_IML : MX_REL) + cc * 4096;
                uint32_t bbx = wb + (combo ? b2 : b1);
                float (*acc)[2][4] = combo ? acc2 : acc1;
                uint32_t Ah[2][4], Al[2][4], Bh[4], Bl[4];
#pragma unroll
                for (int mf = 0; mf < 2; mf++) {
                    LDSM4(Ah[mf], ah + SW(offA[mf] + ks * 32));
                    LDSM4(Al[mf], al + SW(offA[mf] + ks * 32));
                }
                LDSM4(Bh, bbx + SW(offB + ks * 32));
                LDSM4(Bl, bbx + 8192 + SW(offB + ks * 32));
#pragma unroll
                for (int mf = 0; mf < 2; mf++)
#pragma unroll
                    for (int nf = 0; nf < 2; nf++) {
                        MMA4(acc[mf][nf], Ah[mf], Bh[nf*2], Bh[nf*2+1]);
                        MMA4(acc[mf][nf], Al[mf], Bh[nf*2], Bh[nf*2+1]);
                        MMA4(acc[mf][nf], Ah[mf], Bl[nf*2], Bl[nf*2+1]);
                    }
            }
        }
        __syncthreads();
        if (cc + 1 < 4) {
            MIX_LOADW((cc + 1) * 64);
            CP_WAIT0();
            __syncthreads();
        }
    }
#undef MIX_LOADW

    const float sgn = wg ? 1.0f : -1.0f;
    const float sc = (m == 0 ? 1.0f : 2.0f) * (1.0f / (float)M_SIZE);
    __nv_bfloat16* dh = wg ? g_oim_h : g_ore_h;
    __nv_bfloat16* dl = wg ? g_oim_l : g_ore_l;
#pragma unroll
    for (int mf = 0; mf < 2; mf++) {
#pragma unroll
        for (int nf = 0; nf < 2; nf++) {
#pragma unroll
            for (int h = 0; h < 2; h++) {
                int b  = mf*16 + (lane >> 2) + h * 8;
                int oo = o0 + wn*16 + nf*8 + (lane & 3) * 2;
                float v0 = (acc1[mf][nf][h*2]     + sgn * acc2[mf][nf][h*2])     * sc;
                float v1 = (acc1[mf][nf][h*2 + 1] + sgn * acc2[mf][nf][h*2 + 1]) * sc;
                __nv_bfloat16 hh, ll;
                size_t i0 = (size_t)(b * CH + oo) * NMODES + m;
                split_bf16(v0, hh, ll); dh[i0] = hh; dl[i0] = ll;
                size_t i1 = (size_t)(b * CH + oo + 1) * NMODES + m;
                split_bf16(v1, hh, ll); dh[i1] = hh; dl[i1] = ll;
            }
        }
    }
}

// ---------------------------------------------------------------------------
// Inverse folded DFT + butterfly + LeakyReLU + residual.
// Block = 64 rows x 128 t. P = ore x Bic (K=128), Q = oim x Bis (K=128).
// out[t]=x+lrelu(P+Q); out[4096-t]=x+lrelu(P-Q). 8 warps: wg(P/Q) x wr x wc2.
// K loaded upfront: A 64KB + B 128KB = 192KB smem, 1 CTA/SM.
// ---------------------------------------------------------------------------
#define IV_A 0
#define IV_B 65536
#define SMEM_INV (IV_B + 131072)   // 192KB

__global__ void __launch_bounds__(256, 1) k_inv(const float* __restrict__ x,
                                                float* __restrict__ out) {
    extern __shared__ char sm[];
    uint32_t sb = smem_u32(sm);
    const int tid = threadIdx.x, lane = tid & 31, wid = tid >> 5;
    const int wg = wid >> 2, sub = wid & 3;
    const int wr = sub & 1, wc2 = sub >> 1;
    const int t0   = blockIdx.x * 128;
    const int row0 = blockIdx.y * 64;

    // ---- load A (4 planes x 64 rows x K128) + B (4 planes x 128 t x K128) ----
    {
        const __nv_bfloat16* ap[4] = { g_ore_h, g_ore_l, g_oim_h, g_oim_l };
#pragma unroll
        for (int j = 0; j < 16; j++) {
            int f = tid + j * 256;           // 4096
            int p = f >> 10, rem = f & 1023;
            int r = rem >> 4, cw = rem & 15, ch = cw >> 3, cb = cw & 7;
            CP16(sb + IV_A + p * 16384 + ch * 8192 + SW(r * 128 + cb * 16),
                 ap[p] + (size_t)(row0 + r) * NMODES + ch * 64 + cb * 8);
        }
        const __nv_bfloat16* bp[4] = { g_Bic_h, g_Bic_l, g_Bis_h, g_Bis_l };
#pragma unroll
        for (int j = 0; j < 32; j++) {
            int f = tid + j * 256;           // 8192
            int p = f >> 11, rem = f & 2047;
            int t = rem >> 4, cw = rem & 15, ch = cw >> 3, cb = cw & 7;
            CP16(sb + IV_B + p * 32768 + ch * 16384 + SW(t * 128 + cb * 16),
                 bp[p] + (size_t)(t0 + t) * NMODES + ch * 64 + cb * 8);
        }
        CP_COMMIT();
        CP_WAIT0();
    }
    __syncthreads();

    uint32_t offA[2], offB[4];
#pragma unroll
    for (int mf = 0; mf < 2; mf++)
        offA[mf] = (wr*32 + mf*16 + (lane & 15)) * 128 + (lane >> 4) * 16;
#pragma unroll
    for (int p = 0; p < 4; p++)
        offB[p] = (wc2*64 + p*16 + ((lane >> 4) << 3) + (lane & 7)) * 128
                + ((lane >> 3) & 1) * 16;

    const uint32_t abase = sb + IV_A + wg * 32768;   // ore | oim (h at +0, l at +16384)
    const uint32_t bbase = sb + IV_B + wg * 65536;   // Bic | Bis (h at +0, l at +32768)

    float acc[2][8][4];
#pragma unroll
    for (int i = 0; i < 2; i++)
#pragma unroll
        for (int j = 0; j < 8; j++)
#pragma unroll
            for (int q = 0; q < 4; q++) acc[i][j][q] = 0.0f;

#pragma unroll
    for (int ch = 0; ch < 2; ch++) {
#pragma unroll
        for (int ks = 0; ks < 4; ks++) {
            uint32_t Ah[2][4], Al[2][4], Bh[4][4], Bl[4][4];
#pragma unroll
            for (int mf = 0; mf < 2; mf++)
                LDSM4(Ah[mf], abase + ch * 8192 + SW(offA[mf] + ks * 32));
#pragma unroll
            for (int p = 0; p < 4; p++)
                LDSM4(Bh[p], bbase + ch * 16384 + SW(offB[p] + ks * 32));
#pragma unroll
            for (int mf = 0; mf < 2; mf++)
#pragma unroll
                for (int nf = 0; nf < 8; nf++)
                    MMA4(acc[mf][nf], Ah[mf], Bh[nf>>1][(nf&1)*2], Bh[nf>>1][(nf&1)*2+1]);
#pragma unroll
            for (int p = 0; p < 4; p++)
                LDSM4(Bl[p], bbase + 32768 + ch * 16384 + SW(offB[p] + ks * 32));
#pragma unroll
            for (int mf = 0; mf < 2; mf++)
#pragma unroll
                for (int nf = 0; nf < 8; nf++)
                    MMA4(acc[mf][nf], Ah[mf], Bl[nf>>1][(nf&1)*2], Bl[nf>>1][(nf&1)*2+1]);
#pragma unroll
            for (int mf = 0; mf < 2; mf++)
                LDSM4(Al[mf], abase + 16384 + ch * 8192 + SW(offA[mf] + ks * 32));
#pragma unroll
            for (int mf = 0; mf < 2; mf++)
#pragma unroll
                for (int nf = 0; nf < 8; nf++)
                    MMA4(acc[mf][nf], Al[mf], Bh[nf>>1][(nf&1)*2], Bh[nf>>1][(nf&1)*2+1]);
        }
    }

    // ---- butterfly through smem ----
    __syncthreads();
    float (*sPQ)[258] = (float(*)[258])sm;
#pragma unroll
    for (int mf = 0; mf < 2; mf++) {
        int r = wr*32 + mf*16 + (lane >> 2);
#pragma unroll
        for (int nf = 0; nf < 8; nf++) {
            int col = wc2*64 + nf*8 + (lane & 3) * 2 + wg * 128;
            sPQ[r][col]     = acc[mf][nf][0];
            sPQ[r][col + 1] = acc[mf][nf][1];
            sPQ[r + 8][col]     = acc[mf][nf][2];
            sPQ[r + 8][col + 1] = acc[mf][nf][3];
        }
    }
    __syncthreads();
    for (int f = tid; f < 64 * 128; f += 256) {
        int r = f >> 7, tl = f & 127;
        float P = sPQ[r][tl], Q = sPQ[r][tl + 128];
        int row = row0 + r, t = t0 + tl;
        size_t fi = (size_t)row * M_SIZE + t;
        out[fi] = x[fi] + lrelu(P + Q);
        if (t) {
            size_t mi = (size_t)row * M_SIZE + (M_SIZE - t);
            out[mi] = x[mi] + lrelu(P - Q);
        }
    }
}

// ---------------------------------------------------------------------------
// t = 2048 column: out = x + lrelu( sum_m c_re[m] * (-1)^m )
// ---------------------------------------------------------------------------
__global__ void k_t2048(const float* __restrict__ x, float* __restrict__ out) {
    int row = blockIdx.x * blockDim.x + threadIdx.x;
    float sum = 0.f;
#pragma unroll 4
    for (int m = 0; m < NMODES; m++) {
        size_t i = (size_t)row * NMODES + m;
        float cre = __bfloat162float(g_ore_h[i]) + __bfloat162float(g_ore_l[i]);
        sum += (m & 1) ? -cre : cre;
    }
    size_t idx = (size_t)row * M_SIZE + 2048;
    out[idx] = x[idx] + lrelu(sum);
}

// ---------------------------------------------------------------------------
extern "C" void kernel_launch(void* const* d_in, const int* in_sizes, int n_in,
                              void* d_out, int out_size) {
    (void)in_sizes; (void)n_in; (void)out_size;
    const float*  x  = (const float*)d_in[0];
    const float2* w2 = (const float2*)d_in[1];
    float* out = (float*)d_out;

    cudaFuncSetAttribute(k_fwd,    cudaFuncAttributeMaxDynamicSharedMemorySize, SMEM_GEMM);
    cudaFuncSetAttribute(k_inv,    cudaFuncAttributeMaxDynamicSharedMemorySize, SMEM_INV);
    cudaFuncSetAttribute(k_mixmma, cudaFuncAttributeMaxDynamicSharedMemorySize, SMEM_MIX);

    k_xsplit_fold<<<NROWS, 256>>>(x);
    k_basis_fwd<<<(NMODES * TH) / 256, 256>>>();
    k_basis_inv<<<(TH * NMODES) / 256, 256>>>();
    k_wtransp<<<dim3(CH / 64, NMODES / 32, CH), 256>>>(w2);
    k_fwd<<<dim3(NROWS / 64, 2), 256, SMEM_GEMM>>>(x);
    k_mixmma<<<dim3(NMODES, CH / 64), 256, SMEM_MIX>>>();
    k_inv<<<dim3(TH / 128, NROWS / 64), 256, SMEM_INV>>>(x, out);
    k_t2048<<<NROWS / 256, 256>>>(x, out);
}

// round 11
// speedup vs baseline: 1.1929x; 1.1929x over previous
#include <cuda_runtime.h>
#include <cuda_bf16.h>
#include <stdint.h>

#define M_SIZE 4096
#define NMODES 128
#define BATCH  32
#define CH     256
#define NROWS  (BATCH*CH)   // 8192
#define NC     (2*NMODES)   // 256

// ---------------- device scratch (allocation-free globals) ----------------
__device__ __nv_bfloat16 g_basis_h[(size_t)M_SIZE*NC];   // [t][c]  (inv B)
__device__ __nv_bfloat16 g_basis_l[(size_t)M_SIZE*NC];
__device__ __nv_bfloat16 g_basisT_h[(size_t)NC*M_SIZE];  // [c][t]  (fwd B)
__device__ __nv_bfloat16 g_basisT_l[(size_t)NC*M_SIZE];
__device__ __nv_bfloat16 g_xT_h[(size_t)NC*NROWS];       // xft planes [c][row]
__device__ __nv_bfloat16 g_xT_l[(size_t)NC*NROWS];
// weight planes [m][o][i] bf16 hi/lo
__device__ __nv_bfloat16 gWre_h[(size_t)NMODES*CH*CH], gWre_l[(size_t)NMODES*CH*CH];
__device__ __nv_bfloat16 gWim_h[(size_t)NMODES*CH*CH], gWim_l[(size_t)NMODES*CH*CH];
__device__ __nv_bfloat16 g_oft_h[(size_t)NROWS*NC];      // [row][c] scaled
__device__ __nv_bfloat16 g_oft_l[(size_t)NROWS*NC];

// ---------------- helpers ----------------
__device__ __forceinline__ uint32_t smem_u32(const void* p) {
    uint32_t a;
    asm("{ .reg .u64 t; cvta.to.shared.u64 t, %1; cvt.u32.u64 %0, t; }" : "=r"(a) : "l"(p));
    return a;
}
#define SW(o) ((uint32_t)(o) ^ ((((uint32_t)(o)) >> 3) & 0x70))

#define CP16(d, s)  asm volatile("cp.async.cg.shared.global [%0], [%1], 16;" :: "r"(d), "l"(s))
#define CP_COMMIT() asm volatile("cp.async.commit_group;")
#define CP_WAIT0()  asm volatile("cp.async.wait_group 0;")

#define LDSM4(R, addr) \
    asm volatile("ldmatrix.sync.aligned.m8n8.x4.shared.b16 {%0,%1,%2,%3}, [%4];" \
        : "=r"((R)[0]), "=r"((R)[1]), "=r"((R)[2]), "=r"((R)[3]) : "r"(addr))

#define MMA4(C, A, b0, b1) \
    asm volatile("mma.sync.aligned.m16n8k16.row.col.f32.bf16.bf16.f32 " \
        "{%0,%1,%2,%3},{%4,%5,%6,%7},{%8,%9},{%0,%1,%2,%3};" \
        : "+f"((C)[0]), "+f"((C)[1]), "+f"((C)[2]), "+f"((C)[3]) \
        : "r"((A)[0]), "r"((A)[1]), "r"((A)[2]), "r"((A)[3]), "r"(b0), "r"(b1))

__device__ __forceinline__ void split_bf16(float v, __nv_bfloat16& h, __nv_bfloat16& l) {
    h = __float2bfloat16(v);
    l = __float2bfloat16(v - __bfloat162float(h));
}
__device__ __forceinline__ uint2 pack4(__nv_bfloat16 a, __nv_bfloat16 b,
                                       __nv_bfloat16 c, __nv_bfloat16 d) {
    __nv_bfloat162 p = __halves2bfloat162(a, b), q = __halves2bfloat162(c, d);
    return make_uint2(*(uint32_t*)&p, *(uint32_t*)&q);
}

// ---------------------------------------------------------------------------
// Basis tables
// ---------------------------------------------------------------------------
__global__ void k_basis_a() {   // [t][c]
    int idx = blockIdx.x * blockDim.x + threadIdx.x;
    int t = idx >> 7, m = idx & 127;
    int r = (t * m) & (M_SIZE - 1);
    float s, c;
    sincospif((float)r * (1.0f / 2048.0f), &s, &c);
    __nv_bfloat16 ch, cl, sh, sl;
    split_bf16(c, ch, cl); split_bf16(-s, sh, sl);
    size_t b = (size_t)t * NC + 2 * m;
    *(__nv_bfloat162*)&g_basis_h[b] = __halves2bfloat162(ch, sh);
    *(__nv_bfloat162*)&g_basis_l[b] = __halves2bfloat162(cl, sl);
}
__global__ void k_basis_b() {   // [c][t]
    int idx = blockIdx.x * blockDim.x + threadIdx.x;
    int m = idx >> 12, t = idx & 4095;
    int r = (t * m) & (M_SIZE - 1);
    float s, c;
    sincospif((float)r * (1.0f / 2048.0f), &s, &c);
    __nv_bfloat16 ch, cl, sh, sl;
    split_bf16(c, ch, cl); split_bf16(-s, sh, sl);
    g_basisT_h[(size_t)(2*m)   * M_SIZE + t] = ch;
    g_basisT_h[(size_t)(2*m+1) * M_SIZE + t] = sh;
    g_basisT_l[(size_t)(2*m)   * M_SIZE + t] = cl;
    g_basisT_l[(size_t)(2*m+1) * M_SIZE + t] = sl;
}

// ---------------------------------------------------------------------------
// Weight transpose: w2[o][i][m] float2 -> planes [m][o][i] bf16 hi/lo.
// ---------------------------------------------------------------------------
__global__ void __launch_bounds__(256) k_wtransp(const float2* __restrict__ w2) {
    __shared__ float2 s[64][33];
    const int o  = blockIdx.z;
    const int i0 = blockIdx.x * 64;
    const int m0 = blockIdx.y * 32;
    const int tid = threadIdx.x;
#pragma unroll
    for (int j = 0; j < 8; j++) {
        int f = tid + j * 256;
        int ii = f >> 5, ml = f & 31;
        s[ii][ml] = w2[((size_t)o * CH + i0 + ii) * NMODES + m0 + ml];
    }
    __syncthreads();
#pragma unroll
    for (int j = 0; j < 2; j++) {
        int f = tid + j * 256;
        int ml = f >> 4, ig = (f & 15) * 4;
        float2 v0 = s[ig][ml], v1 = s[ig+1][ml], v2 = s[ig+2][ml], v3 = s[ig+3][ml];
        size_t dst = ((size_t)(m0 + ml) * CH + o) * CH + i0 + ig;
        __nv_bfloat16 h0,l0,h1,l1,h2,l2,h3,l3;
        split_bf16(v0.x,h0,l0); split_bf16(v1.x,h1,l1);
        split_bf16(v2.x,h2,l2); split_bf16(v3.x,h3,l3);
        *(uint2*)&gWre_h[dst] = pack4(h0,h1,h2,h3);
        *(uint2*)&gWre_l[dst] = pack4(l0,l1,l2,l3);
        split_bf16(v0.y,h0,l0); split_bf16(v1.y,h1,l1);
        split_bf16(v2.y,h2,l2); split_bf16(v3.y,h3,l3);
        *(uint2*)&gWim_h[dst] = pack4(h0,h1,h2,h3);
        *(uint2*)&gWim_l[dst] = pack4(l0,l1,l2,l3);
    }
}

// ---------------------------------------------------------------------------
// Forward DFT (R6-proven 146us loop): xT[c][row] = sum_k x[row][k]*basisT[c][k]
// 256 threads, 8 warps 2x4 (warp 64x32), block 128x128, K-chunk 64.
// A converted inline; epilogue writes bf16 hi/lo planes.
// ---------------------------------------------------------------------------
#define F_AH 0
#define F_AL 16384
#define F_BH 32768
#define F_BL 49152
#define FBUF 65536
#define SMEM_FWD (2*FBUF)   // 128KB, 1 CTA/SM

__global__ void __launch_bounds__(256, 1) k_fwd(const float* __restrict__ x) {
    extern __shared__ char sm[];
    uint32_t sb = smem_u32(sm);
    const int tid = threadIdx.x, lane = tid & 31, wid = tid >> 5;
    const int wm = wid & 1, wn = wid >> 1;
    const int row0 = blockIdx.x * 128;
    const int c0   = blockIdx.y * 128;

    uint32_t offA[4], offB[2];
#pragma unroll
    for (int mf = 0; mf < 4; mf++)
        offA[mf] = (wm*64 + mf*16 + (lane & 15)) * 128 + (lane >> 4) * 16;
#pragma unroll
    for (int p = 0; p < 2; p++)
        offB[p] = (wn*32 + p*16 + ((lane >> 4) << 3) + (lane & 7)) * 128
                + ((lane >> 3) & 1) * 16;

    float acc[4][4][4];
#pragma unroll
    for (int i = 0; i < 4; i++)
#pragma unroll
        for (int j = 0; j < 4; j++)
#pragma unroll
            for (int q = 0; q < 4; q++) acc[i][j][q] = 0.0f;

    // ---- preload chunk 0 ----
    {
        const int k0 = 0;
#pragma unroll
        for (int j = 0; j < 8; j++) {
            int f = tid + j * 256;
            int plane = f >> 10, r = (f >> 3) & 127, cb = f & 7;
            const __nv_bfloat16* src = (plane ? g_basisT_l : g_basisT_h)
                                     + (size_t)(c0 + r) * M_SIZE + k0 + cb * 8;
            CP16(sb + F_BH + plane * 16384 + SW(r * 128 + cb * 16), src);
        }
        CP_COMMIT();
#pragma unroll
        for (int it = 0; it < 8; it++) {
            int f = tid + it * 256;
            int r = f >> 4, q = f & 15;
            float4 v = *(const float4*)&x[(size_t)(row0 + r) * M_SIZE + k0 + q * 4];
            __nv_bfloat16 h0,l0,h1,l1,h2,l2,h3,l3;
            split_bf16(v.x,h0,l0); split_bf16(v.y,h1,l1);
            split_bf16(v.z,h2,l2); split_bf16(v.w,h3,l3);
            uint32_t off = SW(r * 128 + q * 8);
            *(uint2*)(sm + F_AH + off) = pack4(h0,h1,h2,h3);
            *(uint2*)(sm + F_AL + off) = pack4(l0,l1,l2,l3);
        }
        CP_WAIT0();
    }
    __syncthreads();

    const int NCHUNK = M_SIZE / 64;
    for (int cc = 0; cc < NCHUNK; cc++) {
        uint32_t bb  = sb + (cc & 1) * FBUF;
        char*    nbp = sm + ((cc + 1) & 1) * FBUF;
        uint32_t nbb = sb + ((cc + 1) & 1) * FBUF;
        bool pf = (cc + 1 < NCHUNK);
        float4 va[8];
        int rpf[8], qpf[8];
        if (pf) {
            const int k1 = (cc + 1) * 64;
#pragma unroll
            for (int j = 0; j < 8; j++) {
                int f = tid + j * 256;
                int plane = f >> 10, r = (f >> 3) & 127, cb = f & 7;
                const __nv_bfloat16* src = (plane ? g_basisT_l : g_basisT_h)
                                         + (size_t)(c0 + r) * M_SIZE + k1 + cb * 8;
                CP16(nbb + F_BH + plane * 16384 + SW(r * 128 + cb * 16), src);
            }
            CP_COMMIT();
#pragma unroll
            for (int it = 0; it < 8; it++) {
                int f = tid + it * 256;
                rpf[it] = f >> 4; qpf[it] = f & 15;
                va[it] = *(const float4*)&x[(size_t)(row0 + rpf[it]) * M_SIZE + k1 + qpf[it] * 4];
            }
        }
#pragma unroll
        for (int ks = 0; ks < 4; ks++) {
            uint32_t Af[4][4], Bh[2][4], Bo[2][4];
#pragma unroll
            for (int mf = 0; mf < 4; mf++) LDSM4(Af[mf], bb + F_AH + SW(offA[mf] + ks * 32));
#pragma unroll
            for (int p = 0; p < 2; p++)    LDSM4(Bh[p],  bb + F_BH + SW(offB[p] + ks * 32));
#pragma unroll
            for (int mf = 0; mf < 4; mf++)
#pragma unroll
                for (int nf = 0; nf < 4; nf++)
                    MMA4(acc[mf][nf], Af[mf], Bh[nf>>1][(nf&1)*2], Bh[nf>>1][(nf&1)*2+1]);
#pragma unroll
            for (int p = 0; p < 2; p++)    LDSM4(Bo[p],  bb + F_BL + SW(offB[p] + ks * 32));
#pragma unroll
            for (int mf = 0; mf < 4; mf++)
#pragma unroll
                for (int nf = 0; nf < 4; nf++)
                    MMA4(acc[mf][nf], Af[mf], Bo[nf>>1][(nf&1)*2], Bo[nf>>1][(nf&1)*2+1]);
#pragma unroll
            for (int mf = 0; mf < 4; mf++) LDSM4(Af[mf], bb + F_AL + SW(offA[mf] + ks * 32));
#pragma unroll
            for (int mf = 0; mf < 4; mf++)
#pragma unroll
                for (int nf = 0; nf < 4; nf++)
                    MMA4(acc[mf][nf], Af[mf], Bh[nf>>1][(nf&1)*2], Bh[nf>>1][(nf&1)*2+1]);
        }
        if (pf) {
#pragma unroll
            for (int it = 0; it < 8; it++) {
                float4 v = va[it];
                __nv_bfloat16 h0,l0,h1,l1,h2,l2,h3,l3;
                split_bf16(v.x,h0,l0); split_bf16(v.y,h1,l1);
                split_bf16(v.z,h2,l2); split_bf16(v.w,h3,l3);
                uint32_t off = SW(rpf[it] * 128 + qpf[it] * 8);
                *(uint2*)(nbp + F_AH + off) = pack4(h0,h1,h2,h3);
                *(uint2*)(nbp + F_AL + off) = pack4(l0,l1,l2,l3);
            }
        }
        CP_WAIT0();
        __syncthreads();
    }
    // ---- epilogue: split + write bf16 planes xT[c][row] ----
#pragma unroll
    for (int mf = 0; mf < 4; mf++) {
        int row = row0 + wm*64 + mf*16 + (lane >> 2);
#pragma unroll
        for (int nf = 0; nf < 4; nf++) {
            int col = c0 + wn*32 + nf*8 + (lane & 3) * 2;
#pragma unroll
            for (int q = 0; q < 4; q++) {
                int cc2 = col + (q & 1);
                int rr2 = row + (q >> 1) * 8;
                __nv_bfloat16 h, l;
                split_bf16(acc[mf][nf][q], h, l);
                g_xT_h[(size_t)cc2 * NROWS + rr2] = h;
                g_xT_l[(size_t)cc2 * NROWS + rr2] = l;
            }
        }
    }
}

// ---------------------------------------------------------------------------
// MMA mode mixing (R9-proven). CTA = (mode m, 64-wide o slice). M=32,N=64,K=256.
// Dual accumulators: re = S(XreWre) - S(XimWim); im = S(XreWim) + S(XimWre).
// ---------------------------------------------------------------------------
#define MX_REH 0
#define MX_REL 16384
#define MX_IMH 32768
#define MX_IML 49152
#define MW_BASE 65536
#define SMEM_MIX (MW_BASE + 32768)   // 96KB

__global__ void __launch_bounds__(256, 2) k_mixmma() {
    extern __shared__ char sm[];
    uint32_t sb = smem_u32(sm);
    const int tid = threadIdx.x, lane = tid & 31, wid = tid >> 5;
    const int wg = wid >> 2, wn = wid & 3;
    const int m  = blockIdx.x;
    const int o0 = blockIdx.y * 64;

#define MIX_LOADW(kk) do {                                                        \
    _Pragma("unroll")                                                             \
    for (int j = 0; j < 8; j++) {                                                 \
        int f = tid + j * 256;                                                    \
        int p = f >> 9, r = (f >> 3) & 63, cb = f & 7;                            \
        const __nv_bfloat16* src = (p == 0) ? gWre_h : (p == 1) ? gWre_l          \
                                 : (p == 2) ? gWim_h : gWim_l;                    \
        CP16(sb + MW_BASE + p * 8192 + SW(r * 128 + cb * 16),                     \
             src + ((size_t)m * CH + o0 + r) * CH + (kk) + cb * 8);               \
    }                                                                             \
    CP_COMMIT();                                                                  \
} while (0)

    {
        const __nv_bfloat16* srcs[4] = {
            g_xT_h + (size_t)(2 * m)     * NROWS,
            g_xT_l + (size_t)(2 * m)     * NROWS,
            g_xT_h + (size_t)(2 * m + 1) * NROWS,
            g_xT_l + (size_t)(2 * m + 1) * NROWS };
#pragma unroll
        for (int j = 0; j < 16; j++) {
            int f = tid + j * 256;
            int p = f >> 10, rem = f & 1023;
            int b = rem >> 5, cb32 = rem & 31;
            int chunk = cb32 >> 3, cb = cb32 & 7;
            CP16(sb + p * 16384 + chunk * 4096 + SW(b * 128 + cb * 16),
                 srcs[p] + (size_t)b * CH + cb32 * 8);
        }
        MIX_LOADW(0);
        CP_WAIT0();
    }
    __syncthreads();

    uint32_t offA[2], offB;
#pragma unroll
    for (int mf = 0; mf < 2; mf++)
        offA[mf] = (mf*16 + (lane & 15)) * 128 + (lane >> 4) * 16;
    offB = (wn*16 + ((lane >> 4) << 3) + (lane & 7)) * 128 + ((lane >> 3) & 1) * 16;

    const uint32_t b1 = wg ? 16384u : 0u;
    const uint32_t b2 = wg ? 0u : 16384u;

    float acc1[2][2][4], acc2[2][2][4];
#pragma unroll
    for (int i = 0; i < 2; i++)
#pragma unroll
        for (int j = 0; j < 2; j++)
#pragma unroll
            for (int q = 0; q < 4; q++) { acc1[i][j][q] = 0.0f; acc2[i][j][q] = 0.0f; }

    for (int cc = 0; cc < 4; cc++) {
        uint32_t wb = sb + MW_BASE;
#pragma unroll
        for (int ks = 0; ks < 4; ks++) {
#pragma unroll
            for (int combo = 0; combo < 2; combo++) {
                uint32_t ah = sb + (combo ? MX_IMH : MX_REH) + cc * 4096;
                uint32_t al = sb + (combo ? MX_IML : MX_REL) + cc * 4096;
                uint32_t bbx = wb + (combo ? b2 : b1);
                float (*acc)[2][4] = combo ? acc2 : acc1;
                uint32_t Ah[2][4], Al[2][4], Bh[4], Bl[4];
#pragma unroll
                for (int mf = 0; mf < 2; mf++) {
                    LDSM4(Ah[mf], ah + SW(offA[mf] + ks * 32));
                    LDSM4(Al[mf], al + SW(offA[mf] + ks * 32));
                }
                LDSM4(Bh, bbx + SW(offB + ks * 32));
                LDSM4(Bl, bbx + 8192 + SW(offB + ks * 32));
#pragma unroll
                for (int mf = 0; mf < 2; mf++)
#pragma unroll
                    for (int nf = 0; nf < 2; nf++) {
                        MMA4(acc[mf][nf], Ah[mf], Bh[nf*2], Bh[nf*2+1]);
                        MMA4(acc[mf][nf], Al[mf], Bh[nf*2], Bh[nf*2+1]);
                        MMA4(acc[mf][nf], Ah[mf], Bl[nf*2], Bl[nf*2+1]);
                    }
            }
        }
        __syncthreads();
        if (cc + 1 < 4) {
            MIX_LOADW((cc + 1) * 64);
            CP_WAIT0();
            __syncthreads();
        }
    }
#undef MIX_LOADW

    const float sgn = wg ? 1.0f : -1.0f;
    const float sc = (m == 0 ? 1.0f : 2.0f) * (1.0f / (float)M_SIZE);
    const int cidx = 2 * m + wg;
#pragma unroll
    for (int mf = 0; mf < 2; mf++) {
#pragma unroll
        for (int nf = 0; nf < 2; nf++) {
#pragma unroll
            for (int h = 0; h < 2; h++) {
                int b  = mf*16 + (lane >> 2) + h * 8;
                int oo = o0 + wn*16 + nf*8 + (lane & 3) * 2;
                float v0 = (acc1[mf][nf][h*2]     + sgn * acc2[mf][nf][h*2])     * sc;
                float v1 = (acc1[mf][nf][h*2 + 1] + sgn * acc2[mf][nf][h*2 + 1]) * sc;
                __nv_bfloat16 hh, ll;
                size_t i0 = ((size_t)b * CH + oo) * NC + cidx;
                split_bf16(v0, hh, ll); g_oft_h[i0] = hh; g_oft_l[i0] = ll;
                size_t i1 = ((size_t)b * CH + oo + 1) * NC + cidx;
                split_bf16(v1, hh, ll); g_oft_h[i1] = hh; g_oft_l[i1] = ll;
            }
        }
    }
}

// ---------------------------------------------------------------------------
// Inverse DFT + LeakyReLU + residual (R8/R9-proven).
// 256 threads; block 64 rows x 128 t; warp grid 2x4, warp tile 32x32.
// ---------------------------------------------------------------------------
#define P_AH 0
#define P_AL 8192
#define P_BH 16384
#define P_BL 32768
#define BUFB 49152
#define SMEM_GEMM (2*BUFB)   // 96KB -> 2 CTAs/SM

__global__ void __launch_bounds__(256, 2) k_inv(const float* __restrict__ x,
                                                float* __restrict__ out) {
    extern __shared__ char sm[];
    uint32_t sb = smem_u32(sm);
    const int tid = threadIdx.x, lane = tid & 31, wid = tid >> 5;
    const int wr = wid & 1, wc = wid >> 1;
    const int t0   = blockIdx.x * 128;
    const int row0 = blockIdx.y * 64;

    uint32_t offA[2], offB[2];
#pragma unroll
    for (int mf = 0; mf < 2; mf++)
        offA[mf] = (wr*32 + mf*16 + (lane & 15)) * 128 + (lane >> 4) * 16;
#pragma unroll
    for (int p = 0; p < 2; p++)
        offB[p] = (wc*32 + p*16 + ((lane >> 4) << 3) + (lane & 7)) * 128
                + ((lane >> 3) & 1) * 16;

    float acc[2][4][4];
#pragma unroll
    for (int i = 0; i < 2; i++)
#pragma unroll
        for (int j = 0; j < 4; j++)
#pragma unroll
            for (int q = 0; q < 4; q++) acc[i][j][q] = 0.0f;

#define INV_LOAD(dstb, kk) do {                                                   \
    _Pragma("unroll")                                                             \
    for (int j = 0; j < 4; j++) {                                                 \
        int f = tid + j * 256;                                                    \
        int plane = f >> 9, r = (f >> 3) & 63, cb = f & 7;                        \
        const __nv_bfloat16* src = (plane ? g_oft_l : g_oft_h)                    \
                                 + (size_t)(row0 + r) * NC + (kk) + cb * 8;       \
        CP16((dstb) + P_AH + plane * 8192 + SW(r * 128 + cb * 16), src);          \
    }                                                                             \
    _Pragma("unroll")                                                             \
    for (int j = 0; j < 8; j++) {                                                 \
        int f = tid + j * 256;                                                    \
        int plane = f >> 10, r = (f >> 3) & 127, cb = f & 7;                      \
        const __nv_bfloat16* src = (plane ? g_basis_l : g_basis_h)                \
                                 + (size_t)(t0 + r) * NC + (kk) + cb * 8;         \
        CP16((dstb) + P_BH + plane * 16384 + SW(r * 128 + cb * 16), src);         \
    }                                                                             \
    CP_COMMIT();                                                                  \
} while (0)

    INV_LOAD(sb, 0);
    CP_WAIT0();
    __syncthreads();

    const int NCHUNK = NC / 64;
    for (int cc = 0; cc < NCHUNK; cc++) {
        uint32_t bb  = sb + (cc & 1) * BUFB;
        uint32_t nbb = sb + ((cc + 1) & 1) * BUFB;
        if (cc + 1 < NCHUNK) INV_LOAD(nbb, (cc + 1) * 64);
#pragma unroll
        for (int ks = 0; ks < 4; ks++) {
            uint32_t Af[2][4], Bh[2][4], Bo[2][4];
#pragma unroll
            for (int mf = 0; mf < 2; mf++) LDSM4(Af[mf], bb + P_AH + SW(offA[mf] + ks * 32));
#pragma unroll
            for (int p = 0; p < 2; p++)    LDSM4(Bh[p],  bb + P_BH + SW(offB[p] + ks * 32));
#pragma unroll
            for (int mf = 0; mf < 2; mf++)
#pragma unroll
                for (int nf = 0; nf < 4; nf++)
                    MMA4(acc[mf][nf], Af[mf], Bh[nf>>1][(nf&1)*2], Bh[nf>>1][(nf&1)*2+1]);
#pragma unroll
            for (int p = 0; p < 2; p++)    LDSM4(Bo[p],  bb + P_BL + SW(offB[p] + ks * 32));
#pragma unroll
            for (int mf = 0; mf < 2; mf++)
#pragma unroll
                for (int nf = 0; nf < 4; nf++)
                    MMA4(acc[mf][nf], Af[mf], Bo[nf>>1][(nf&1)*2], Bo[nf>>1][(nf&1)*2+1]);
#pragma unroll
            for (int mf = 0; mf < 2; mf++) LDSM4(Af[mf], bb + P_AL + SW(offA[mf] + ks * 32));
#pragma unroll
            for (int mf = 0; mf < 2; mf++)
#pragma unroll
                for (int nf = 0; nf < 4; nf++)
                    MMA4(acc[mf][nf], Af[mf], Bh[nf>>1][(nf&1)*2], Bh[nf>>1][(nf&1)*2+1]);
        }
        CP_WAIT0();
        __syncthreads();
    }
#undef INV_LOAD
#pragma unroll
    for (int mf = 0; mf < 2; mf++) {
        int row = row0 + wr*32 + mf*16 + (lane >> 2);
#pragma unroll
        for (int nf = 0; nf < 4; nf++) {
            int tc = t0 + wc*32 + nf*8 + (lane & 3) * 2;
#pragma unroll
            for (int h = 0; h < 2; h++) {
                size_t base = (size_t)(row + h * 8) * M_SIZE + tc;
                float2 xv = *(const float2*)&x[base];
                float v0 = acc[mf][nf][h*2], v1 = acc[mf][nf][h*2+1];
                float2 rv;
                rv.x = xv.x + (v0 >= 0.f ? v0 : 0.2f * v0);
                rv.y = xv.y + (v1 >= 0.f ? v1 : 0.2f * v1);
                *(float2*)&out[base] = rv;
            }
        }
    }
}

// ---------------------------------------------------------------------------
extern "C" void kernel_launch(void* const* d_in, const int* in_sizes, int n_in,
                              void* d_out, int out_size) {
    (void)in_sizes; (void)n_in; (void)out_size;
    const float*  x  = (const float*)d_in[0];
    const float2* w2 = (const float2*)d_in[1];
    float* out = (float*)d_out;

    cudaFuncSetAttribute(k_fwd,    cudaFuncAttributeMaxDynamicSharedMemorySize, SMEM_FWD);
    cudaFuncSetAttribute(k_inv,    cudaFuncAttributeMaxDynamicSharedMemorySize, SMEM_GEMM);
    cudaFuncSetAttribute(k_mixmma, cudaFuncAttributeMaxDynamicSharedMemorySize, SMEM_MIX);

    k_basis_a<<<(M_SIZE * NMODES) / 256, 256>>>();
    k_basis_b<<<(M_SIZE * NMODES) / 256, 256>>>();
    k_wtransp<<<dim3(CH / 64, NMODES / 32, CH), 256>>>(w2);
    k_fwd<<<dim3(NROWS / 128, NC / 128), 256, SMEM_FWD>>>(x);
    k_mixmma<<<dim3(NMODES, CH / 64), 256, SMEM_MIX>>>();
    k_inv<<<dim3(M_SIZE / 128, NROWS / 64), 256, SMEM_GEMM>>>(x, out);
}